// round 2
// baseline (speedup 1.0000x reference)
#include <cuda_runtime.h>
#include <cuda_bf16.h>
#include <math.h>

// Problem constants
#define Bc   8
#define Sc   1024
#define Ec   512
#define Hc   8
#define HDc  64
#define Pc   32
#define Nt   (Bc*Sc)     // 8192 tokens
#define HIDc 2048

// ---------------- scratch (device globals; allocation-free) ----------------
__device__ float g_qkv[Nt*3*Ec];
__device__ float g_lo[Nt*Ec];
__device__ float g_local[Nt*Ec];
__device__ float g_h1[Nt*Ec];
__device__ float g_offraw[Nt*Hc*Pc];
__device__ int   g_sp[Nt*Pc];
__device__ float g_qd[Nt*Ec];
__device__ float g_kd[Nt*Ec];
__device__ float g_vd[Nt*Ec];
__device__ float g_lattn[Nt*Ec];
__device__ float g_long[Nt*Ec];
__device__ float g_cat[Nt*3*Ec];
__device__ float g_gh[Nt*Ec];
__device__ float g_gate[Nt*Ec];
__device__ float g_x1[Nt*Ec];
__device__ float g_ffnh[Nt*HIDc];
__device__ float g_f[Nt*Ec];
__device__ int   g_vl[Bc];

// ---------------- generic SGEMM: C[M,N] = A[M,K] @ B[N,K]^T + bias ----------
// EPI: 0 none, 1 exact gelu, 2 tanh, 3 sigmoid
// Requires M%128==0, N%128==0, K%8==0 (true for all calls here).
template<int EPI>
__global__ __launch_bounds__(256) void sgemm_nt(
    const float* __restrict__ A, const float* __restrict__ Bw,
    const float* __restrict__ bias, float* __restrict__ C,
    int M, int Nn, int K)
{
    __shared__ float As[8][128];
    __shared__ float Bs[8][128];
    const int tid = threadIdx.x;
    const int row = tid >> 1;          // 0..127
    const int kc  = (tid & 1) * 4;     // 0 or 4
    const int tx  = tid & 15;
    const int ty  = tid >> 4;

    const float* Ap = A  + ((long)blockIdx.y * 128 + row) * (long)K;
    const float* Bp = Bw + ((long)blockIdx.x * 128 + row) * (long)K;

    float acc[8][8];
#pragma unroll
    for (int i = 0; i < 8; i++)
#pragma unroll
        for (int j = 0; j < 8; j++) acc[i][j] = 0.f;

    for (int k0 = 0; k0 < K; k0 += 8) {
        float4 a4 = *reinterpret_cast<const float4*>(Ap + k0 + kc);
        float4 b4 = *reinterpret_cast<const float4*>(Bp + k0 + kc);
        As[kc+0][row] = a4.x; As[kc+1][row] = a4.y; As[kc+2][row] = a4.z; As[kc+3][row] = a4.w;
        Bs[kc+0][row] = b4.x; Bs[kc+1][row] = b4.y; Bs[kc+2][row] = b4.z; Bs[kc+3][row] = b4.w;
        __syncthreads();
#pragma unroll
        for (int kk = 0; kk < 8; kk++) {
            float4 a0 = *reinterpret_cast<const float4*>(&As[kk][ty*8]);
            float4 a1 = *reinterpret_cast<const float4*>(&As[kk][ty*8+4]);
            float4 b0 = *reinterpret_cast<const float4*>(&Bs[kk][tx*8]);
            float4 b1 = *reinterpret_cast<const float4*>(&Bs[kk][tx*8+4]);
            float ar[8] = {a0.x,a0.y,a0.z,a0.w,a1.x,a1.y,a1.z,a1.w};
            float br[8] = {b0.x,b0.y,b0.z,b0.w,b1.x,b1.y,b1.z,b1.w};
#pragma unroll
            for (int i = 0; i < 8; i++)
#pragma unroll
                for (int j = 0; j < 8; j++)
                    acc[i][j] = fmaf(ar[i], br[j], acc[i][j]);
        }
        __syncthreads();
    }

#pragma unroll
    for (int i = 0; i < 8; i++) {
        long r = (long)blockIdx.y * 128 + ty*8 + i;
#pragma unroll
        for (int j = 0; j < 8; j++) {
            int c = blockIdx.x * 128 + tx*8 + j;
            float v = acc[i][j] + bias[c];
            if (EPI == 1)      v = 0.5f * v * (1.f + erff(v * 0.70710678118654752f));
            else if (EPI == 2) v = tanhf(v);
            else if (EPI == 3) v = 1.f / (1.f + expf(-v));
            C[r * Nn + c] = v;
        }
    }
}

// ---------------- local windowed attention: one warp per (token, head) -----
__global__ __launch_bounds__(256) void local_attn_kernel(const int* __restrict__ pad)
{
    int gwarp = (blockIdx.x * blockDim.x + threadIdx.x) >> 5;
    int lane  = threadIdx.x & 31;
    if (gwarp >= Nt * Hc) return;
    int h = gwarp % Hc;
    int n = gwarp / Hc;      // b*S + q
    int b = n / Sc, q = n % Sc;

    const float* base = g_qkv + (long)n * (3*Ec);
    float2 qv = *reinterpret_cast<const float2*>(base + h*HDc + lane*2);

    float sc[4]; bool val[4];
#pragma unroll
    for (int w = 0; w < 4; w++) {
        int kpos = q - 3 + w;
        bool v = (kpos >= 0) && (pad[b*Sc + kpos] == 0);
        float s = 0.f;
        if (v) {
            float2 kv = *reinterpret_cast<const float2*>(
                g_qkv + ((long)(b*Sc + kpos)) * (3*Ec) + Ec + h*HDc + lane*2);
            s = qv.x*kv.x + qv.y*kv.y;
        }
#pragma unroll
        for (int o = 16; o > 0; o >>= 1) s += __shfl_xor_sync(0xffffffffu, s, o);
        sc[w]  = s * 0.125f;   // / sqrt(64)
        val[w] = v;
    }
    float m = -INFINITY;
#pragma unroll
    for (int w = 0; w < 4; w++) if (val[w]) m = fmaxf(m, sc[w]);
    float e[4]; float den = 0.f;
#pragma unroll
    for (int w = 0; w < 4; w++) { e[w] = val[w] ? expf(sc[w] - m) : 0.f; den += e[w]; }

    float2 o = make_float2(0.f, 0.f);
    if (den > 0.f) {
        float inv = 1.f / den;
#pragma unroll
        for (int w = 0; w < 4; w++) {
            if (!val[w]) continue;
            int kpos = q - 3 + w;
            float a = e[w] * inv;
            float2 vv = *reinterpret_cast<const float2*>(
                g_qkv + ((long)(b*Sc + kpos)) * (3*Ec) + 2*Ec + h*HDc + lane*2);
            o.x += a * vv.x; o.y += a * vv.y;
        }
    }
    *reinterpret_cast<float2*>(g_lo + (long)n*Ec + h*HDc + lane*2) = o;
}

// ---------------- valid length per batch ------------------------------------
__global__ void valid_len_kernel(const int* __restrict__ pad)
{
    int b = blockIdx.x;
    __shared__ int cnt;
    if (threadIdx.x == 0) cnt = 0;
    __syncthreads();
    int c = 0;
    for (int s = threadIdx.x; s < Sc; s += blockDim.x) c += (pad[b*Sc + s] != 0);
    atomicAdd(&cnt, c);
    __syncthreads();
    if (threadIdx.x == 0) {
        int v = Sc - cnt;
        g_vl[b] = v < 1 ? 1 : v;
    }
}

// ---------------- sampled positions: 32 lanes per token ---------------------
__global__ void sample_kernel()
{
    int idx = blockIdx.x * blockDim.x + threadIdx.x;
    int n = idx >> 5, p = idx & 31;
    if (n >= Nt) return;
    int b = n / Sc, s = n % Sc;

    float off = 0.f;   // mean over H then *OFFS(=8) == plain sum over H (exact)
#pragma unroll
    for (int h = 0; h < Hc; h++) off += g_offraw[(long)n*(Hc*Pc) + h*Pc + p];

    float pos    = (float)s;
    // fp32 emulation of jnp.linspace(0.1, 0.9, 32), endpoint exact
    float delta  = (0.9f - 0.1f) / 31.0f;
    float anchor = (p == 31) ? 0.9f : fmaf((float)p, delta, 0.1f);
    float samp   = anchor * pos + off;
    float lob    = fmaxf(pos - 256.f, 0.f);
    samp = fminf(fmaxf(samp, lob), pos);
    samp = fminf(samp, (float)(g_vl[b] - 1));
    g_sp[(long)n*Pc + p] = (int)rintf(samp);   // round-half-to-even == jnp.round
}

// ---------------- long deformable attention: one block per token ------------
__global__ __launch_bounds__(256) void long_attn_kernel(const int* __restrict__ pad)
{
    int n = blockIdx.x;            // token index
    int b = n / Sc, q = n % Sc;
    int tid = threadIdx.x, lane = tid & 31, warp = tid >> 5;

    __shared__ float s_sc[Pc];
    __shared__ float s_a[Pc];
    __shared__ int   s_j[Pc];
    if (tid < Pc) s_j[tid] = g_sp[(long)n*Pc + tid];
    __syncthreads();

    const float* qrow = g_qd + (long)n*Ec;
#pragma unroll
    for (int i = 0; i < 4; i++) {
        int p = warp*4 + i;
        int j = s_j[p];
        const float* krow = g_kd + ((long)b*Sc + j)*Ec;
        float s = 0.f;
#pragma unroll
        for (int t = 0; t < 4; t++) {
            float4 a = *reinterpret_cast<const float4*>(qrow + t*128 + lane*4);
            float4 k = *reinterpret_cast<const float4*>(krow + t*128 + lane*4);
            s += a.x*k.x + a.y*k.y + a.z*k.z + a.w*k.w;
        }
#pragma unroll
        for (int o = 16; o > 0; o >>= 1) s += __shfl_xor_sync(0xffffffffu, s, o);
        if (lane == 0) s_sc[p] = s;
    }
    __syncthreads();

    if (tid < Pc) {
        int p = tid;
        int j = s_j[p];
        int rb = q - 3; if (rb < 0) rb = 0;
        bool inv = (pad[b*Sc + j] != 0) || (j > q) || (j >= rb);
        float sc = inv ? -INFINITY : (s_sc[p] / 22.627416997969520780827019587355f);
        float m = sc;
#pragma unroll
        for (int o = 16; o > 0; o >>= 1) m = fmaxf(m, __shfl_xor_sync(0xffffffffu, m, o));
        float e = inv ? 0.f : expf(sc - m);
        float den = e;
#pragma unroll
        for (int o = 16; o > 0; o >>= 1) den += __shfl_xor_sync(0xffffffffu, den, o);
        s_a[p] = (den > 0.f) ? (e / den) : 0.f;
    }
    __syncthreads();

    int d = tid * 2;
    float a0 = 0.f, a1 = 0.f;
    for (int p = 0; p < Pc; p++) {
        float a = s_a[p];
        if (a != 0.f) {
            const float* vrow = g_vd + ((long)b*Sc + s_j[p])*Ec;
            float2 vv = *reinterpret_cast<const float2*>(vrow + d);
            a0 += a * vv.x; a1 += a * vv.y;
        }
    }
    *reinterpret_cast<float2*>(g_lattn + (long)n*Ec + d) = make_float2(a0, a1);
}

// ---------------- concat [x | local | long] ---------------------------------
__global__ void concat_kernel(const float* __restrict__ x)
{
    long i = (long)blockIdx.x * blockDim.x + threadIdx.x;
    if (i >= (long)Nt * (3*Ec)) return;
    long n = i / (3*Ec);
    int  c = (int)(i % (3*Ec));
    float v;
    if (c < Ec)           v = x[n*Ec + c];
    else if (c < 2*Ec)    v = g_local[n*Ec + c - Ec];
    else                  v = g_long[n*Ec + c - 2*Ec];
    g_cat[i] = v;
}

// ---------------- block reduction helper -------------------------------------
__device__ __forceinline__ float block_sum_256(float v)
{
    __shared__ float sh[8];
    int lane = threadIdx.x & 31, w = threadIdx.x >> 5;
#pragma unroll
    for (int o = 16; o > 0; o >>= 1) v += __shfl_xor_sync(0xffffffffu, v, o);
    if (lane == 0) sh[w] = v;
    __syncthreads();
    float r = (lane < 8) ? sh[lane] : 0.f;
    if (w == 0) {
#pragma unroll
        for (int o = 4; o > 0; o >>= 1) r += __shfl_xor_sync(0xffffffffu, r, o);
        if (lane == 0) sh[0] = r;
    }
    __syncthreads();
    float out = sh[0];
    __syncthreads();
    return out;
}

// ---------------- gate fuse + residual + LN1 --------------------------------
__global__ __launch_bounds__(256) void fuse_ln1_kernel(
    const float* __restrict__ x, const float* __restrict__ gW, const float* __restrict__ bW)
{
    int n = blockIdx.x, tid = threadIdx.x;
    long base = (long)n*Ec + tid*2;
    float2 gg = *reinterpret_cast<const float2*>(g_gate + base);
    float2 lc = *reinterpret_cast<const float2*>(g_local + base);
    float2 lg = *reinterpret_cast<const float2*>(g_long + base);
    float2 xx = *reinterpret_cast<const float2*>(x + base);
    float v0 = xx.x + gg.x*lc.x + (1.f - gg.x)*lg.x;
    float v1 = xx.y + gg.y*lc.y + (1.f - gg.y)*lg.y;

    float mean = block_sum_256(v0 + v1) * (1.f/512.f);
    float d0 = v0 - mean, d1 = v1 - mean;
    float var = block_sum_256(d0*d0 + d1*d1) * (1.f/512.f);
    float inv = 1.f / sqrtf(var + 1e-5f);

    int c = tid*2;
    float2 go = *reinterpret_cast<const float2*>(gW + c);
    float2 bo = *reinterpret_cast<const float2*>(bW + c);
    *reinterpret_cast<float2*>(g_x1 + base) =
        make_float2(d0*inv*go.x + bo.x, d1*inv*go.y + bo.y);
}

// ---------------- residual + LN2 (final output) ------------------------------
__global__ __launch_bounds__(256) void ln2_kernel(
    const float* __restrict__ gW, const float* __restrict__ bW, float* __restrict__ out)
{
    int n = blockIdx.x, tid = threadIdx.x;
    long base = (long)n*Ec + tid*2;
    float2 xa = *reinterpret_cast<const float2*>(g_x1 + base);
    float2 fa = *reinterpret_cast<const float2*>(g_f + base);
    float v0 = xa.x + fa.x, v1 = xa.y + fa.y;

    float mean = block_sum_256(v0 + v1) * (1.f/512.f);
    float d0 = v0 - mean, d1 = v1 - mean;
    float var = block_sum_256(d0*d0 + d1*d1) * (1.f/512.f);
    float inv = 1.f / sqrtf(var + 1e-5f);

    int c = tid*2;
    float2 go = *reinterpret_cast<const float2*>(gW + c);
    float2 bo = *reinterpret_cast<const float2*>(bW + c);
    *reinterpret_cast<float2*>(out + base) =
        make_float2(d0*inv*go.x + bo.x, d1*inv*go.y + bo.y);
}

// ---------------- host launcher ----------------------------------------------
static float* sym(const void* s) { void* p = nullptr; cudaGetSymbolAddress(&p, s); return (float*)p; }

extern "C" void kernel_launch(void* const* d_in, const int* in_sizes, int n_in,
                              void* d_out, int out_size)
{
    const float* x    = (const float*)d_in[0];
    const int*   pad  = (const int*)d_in[1];          // bool mask delivered as int32
    const float* in_proj_w = (const float*)d_in[2];
    const float* in_proj_b = (const float*)d_in[3];
    const float* mha_out_w = (const float*)d_in[4];
    const float* mha_out_b = (const float*)d_in[5];
    const float* dq_w = (const float*)d_in[6];
    const float* dq_b = (const float*)d_in[7];
    const float* dk_w = (const float*)d_in[8];
    const float* dk_b = (const float*)d_in[9];
    const float* dv_w = (const float*)d_in[10];
    const float* dv_b = (const float*)d_in[11];
    const float* do_w = (const float*)d_in[12];
    const float* do_b = (const float*)d_in[13];
    const float* off1_w = (const float*)d_in[14];
    const float* off1_b = (const float*)d_in[15];
    const float* off2_w = (const float*)d_in[16];
    const float* off2_b = (const float*)d_in[17];
    const float* gate1_w = (const float*)d_in[18];
    const float* gate1_b = (const float*)d_in[19];
    const float* gate2_w = (const float*)d_in[20];
    const float* gate2_b = (const float*)d_in[21];
    const float* n1_g = (const float*)d_in[22];
    const float* n1_b = (const float*)d_in[23];
    const float* n2_g = (const float*)d_in[24];
    const float* n2_b = (const float*)d_in[25];
    const float* ffn1_w = (const float*)d_in[26];
    const float* ffn1_b = (const float*)d_in[27];
    const float* ffn2_w = (const float*)d_in[28];
    const float* ffn2_b = (const float*)d_in[29];

    float* p_qkv   = sym(g_qkv);
    float* p_lo    = sym(g_lo);
    float* p_local = sym(g_local);
    float* p_h1    = sym(g_h1);
    float* p_offr  = sym(g_offraw);
    float* p_qd    = sym(g_qd);
    float* p_kd    = sym(g_kd);
    float* p_vd    = sym(g_vd);
    float* p_latt  = sym(g_lattn);
    float* p_long  = sym(g_long);
    float* p_cat   = sym(g_cat);
    float* p_gh    = sym(g_gh);
    float* p_gate  = sym(g_gate);
    float* p_x1    = sym(g_x1);
    float* p_ffnh  = sym(g_ffnh);
    float* p_f     = sym(g_f);

    dim3 blk(256);

    // 1) qkv = x @ in_proj_w^T + b   [8192,1536]
    sgemm_nt<0><<<dim3(1536/128, Nt/128), blk>>>(x, in_proj_w, in_proj_b, p_qkv, Nt, 1536, Ec);
    // 2) local windowed attention -> g_lo
    local_attn_kernel<<<(Nt*Hc)/8, blk>>>(pad);
    // 3) local_out = lo @ mha_out_w^T + b
    sgemm_nt<0><<<dim3(Ec/128, Nt/128), blk>>>(p_lo, mha_out_w, mha_out_b, p_local, Nt, Ec, Ec);
    // 4) offset path
    sgemm_nt<1><<<dim3(Ec/128, Nt/128), blk>>>(x, off1_w, off1_b, p_h1, Nt, Ec, Ec);
    sgemm_nt<2><<<dim3(256/128, Nt/128), blk>>>(p_h1, off2_w, off2_b, p_offr, Nt, 256, Ec);
    valid_len_kernel<<<Bc, blk>>>(pad);
    sample_kernel<<<(Nt*Pc)/256, blk>>>();
    // 5) deformable q/k/v projections
    sgemm_nt<0><<<dim3(Ec/128, Nt/128), blk>>>(x, dq_w, dq_b, p_qd, Nt, Ec, Ec);
    sgemm_nt<0><<<dim3(Ec/128, Nt/128), blk>>>(x, dk_w, dk_b, p_kd, Nt, Ec, Ec);
    sgemm_nt<0><<<dim3(Ec/128, Nt/128), blk>>>(x, dv_w, dv_b, p_vd, Nt, Ec, Ec);
    // 6) long attention -> g_lattn
    long_attn_kernel<<<Nt, blk>>>(pad);
    // 7) long_out = lattn @ do_w^T + b
    sgemm_nt<0><<<dim3(Ec/128, Nt/128), blk>>>(p_latt, do_w, do_b, p_long, Nt, Ec, Ec);
    // 8) gate
    concat_kernel<<<(int)(((long)Nt*3*Ec + 255)/256), blk>>>(x);
    sgemm_nt<1><<<dim3(Ec/128, Nt/128), blk>>>(p_cat, gate1_w, gate1_b, p_gh, Nt, Ec, 3*Ec);
    sgemm_nt<3><<<dim3(Ec/128, Nt/128), blk>>>(p_gh, gate2_w, gate2_b, p_gate, Nt, Ec, Ec);
    // 9) fuse + residual + LN1 -> g_x1
    fuse_ln1_kernel<<<Nt, blk>>>(x, n1_g, n1_b);
    // 10) FFN
    sgemm_nt<1><<<dim3(HIDc/128, Nt/128), blk>>>(p_x1, ffn1_w, ffn1_b, p_ffnh, Nt, HIDc, Ec);
    sgemm_nt<0><<<dim3(Ec/128, Nt/128), blk>>>(p_ffnh, ffn2_w, ffn2_b, p_f, Nt, Ec, HIDc);
    // 11) residual + LN2 -> output
    ln2_kernel<<<Nt, blk>>>(n2_g, n2_b, (float*)d_out);
}

// round 3
// speedup vs baseline: 3.1195x; 3.1195x over previous
#include <cuda_runtime.h>
#include <cuda_bf16.h>
#include <math.h>
#include <stdint.h>

// Problem constants
#define Bc   8
#define Sc   1024
#define Ec   512
#define Hc   8
#define HDc  64
#define Pc   32
#define Nt   (Bc*Sc)     // 8192 tokens
#define HIDc 2048

// ---------------- scratch (device globals; allocation-free) ----------------
__device__ float g_qkv[Nt*3*Ec];
__device__ float g_lo[Nt*Ec];
__device__ float g_local[Nt*Ec];
__device__ float g_h1[Nt*Ec];
__device__ float g_offraw[Nt*Hc*Pc];
__device__ int   g_sp[Nt*Pc];
__device__ float g_qd[Nt*Ec];
__device__ float g_kd[Nt*Ec];
__device__ float g_vd[Nt*Ec];
__device__ float g_lattn[Nt*Ec];
__device__ float g_long[Nt*Ec];
__device__ float g_cat[Nt*3*Ec];
__device__ float g_gh[Nt*Ec];
__device__ float g_gate[Nt*Ec];
__device__ float g_x1[Nt*Ec];
__device__ float g_ffnh[Nt*HIDc];
__device__ float g_f[Nt*Ec];
__device__ int   g_vl[Bc];

// ---------------- TF32 helpers ----------------------------------------------
__device__ __forceinline__ uint32_t f2tf(float f) {
    uint32_t u;
    asm("cvt.rna.tf32.f32 %0, %1;" : "=r"(u) : "f"(f));
    return u;
}

__device__ __forceinline__ void mma_tf32(float4& d, const uint32_t* a, const uint32_t* b) {
    asm volatile(
        "mma.sync.aligned.m16n8k8.row.col.f32.tf32.tf32.f32 "
        "{%0,%1,%2,%3}, {%4,%5,%6,%7}, {%8,%9}, {%0,%1,%2,%3};"
        : "+f"(d.x), "+f"(d.y), "+f"(d.z), "+f"(d.w)
        : "r"(a[0]), "r"(a[1]), "r"(a[2]), "r"(a[3]),
          "r"(b[0]), "r"(b[1]));
}

__device__ __forceinline__ float apply_epi(float v, int EPI) {
    if (EPI == 1)      return 0.5f * v * (1.f + erff(v * 0.70710678118654752f));
    else if (EPI == 2) return tanhf(v);
    else if (EPI == 3) return 1.f / (1.f + expf(-v));
    return v;
}

// ---------------- TF32 tensor-core GEMM: C[M,N] = A[M,K] @ B[N,K]^T + bias --
// CTA tile 128x128, ktile 32, 8 warps (warp tile 32(M) x 64(N)).
// EPI: 0 none, 1 exact gelu, 2 tanh, 3 sigmoid.
// Requires M%128==0, N%128==0, K%32==0.
template<int EPI>
__global__ __launch_bounds__(256, 2) void tgemm(
    const float* __restrict__ A, const float* __restrict__ Bw,
    const float* __restrict__ bias, float* __restrict__ C,
    int M, int N, int K)
{
    // layout: float4 index = (2*ks+khi)*129 + row ; .x..w = klo 0..3
    __shared__ uint32_t sA[8*129*4];
    __shared__ uint32_t sB[8*129*4];

    const int t    = threadIdx.x;
    const int lane = t & 31;
    const int w    = t >> 5;
    const int wm   = w & 3;        // 0..3  (M quadrant, 32 rows each)
    const int wn   = w >> 2;       // 0..1  (N half, 64 cols each)
    const long rowBase = (long)blockIdx.y * 128;
    const long colBase = (long)blockIdx.x * 128;

    float4 acc[2][8];
#pragma unroll
    for (int mt = 0; mt < 2; mt++)
#pragma unroll
        for (int nt = 0; nt < 8; nt++) acc[mt][nt] = make_float4(0.f,0.f,0.f,0.f);

    const int rrow = t >> 3;       // 0..31 (row within 32-row group)
    const int kq8  = t & 7;        // 0..7  -> k offset kq8*4 (== 2*ks+khi)
    const float* Ag = A  + (rowBase + rrow) * (long)K + kq8 * 4;
    const float* Bg = Bw + (colBase + rrow) * (long)K + kq8 * 4;

    for (int kt = 0; kt < K; kt += 32) {
        // ---- load gmem -> tf32 -> smem (coalesced 128B per warp-row) ----
#pragma unroll
        for (int i = 0; i < 4; i++) {
            float4 av = *reinterpret_cast<const float4*>(Ag + (long)(32*i) * K + kt);
            uint4 ua = make_uint4(f2tf(av.x), f2tf(av.y), f2tf(av.z), f2tf(av.w));
            reinterpret_cast<uint4*>(sA)[kq8*129 + rrow + 32*i] = ua;
            float4 bv = *reinterpret_cast<const float4*>(Bg + (long)(32*i) * K + kt);
            uint4 ub = make_uint4(f2tf(bv.x), f2tf(bv.y), f2tf(bv.z), f2tf(bv.w));
            reinterpret_cast<uint4*>(sB)[kq8*129 + rrow + 32*i] = ub;
        }
        __syncthreads();

        // ---- 4 k-steps of m16n8k8 ----
        const int c = lane & 3;
        const int q = lane >> 2;
#pragma unroll
        for (int s = 0; s < 4; s++) {
            uint32_t af[2][4];
            uint32_t bf[8][2];
#pragma unroll
            for (int mt = 0; mt < 2; mt++) {
                int m = wm*32 + mt*16 + q;
                af[mt][0] = sA[((2*s+0)*129 + m    )*4 + c];
                af[mt][1] = sA[((2*s+0)*129 + m + 8)*4 + c];
                af[mt][2] = sA[((2*s+1)*129 + m    )*4 + c];
                af[mt][3] = sA[((2*s+1)*129 + m + 8)*4 + c];
            }
#pragma unroll
            for (int nt = 0; nt < 8; nt++) {
                int n = wn*64 + nt*8 + q;
                bf[nt][0] = sB[((2*s+0)*129 + n)*4 + c];
                bf[nt][1] = sB[((2*s+1)*129 + n)*4 + c];
            }
#pragma unroll
            for (int mt = 0; mt < 2; mt++)
#pragma unroll
                for (int nt = 0; nt < 8; nt++)
                    mma_tf32(acc[mt][nt], af[mt], bf[nt]);
        }
        __syncthreads();
    }

    // ---- epilogue: bias + activation, float2 stores ----
    const int c2 = (lane & 3) * 2;
    const int q  = lane >> 2;
#pragma unroll
    for (int mt = 0; mt < 2; mt++) {
        long r0 = rowBase + wm*32 + mt*16 + q;
        long r1 = r0 + 8;
#pragma unroll
        for (int nt = 0; nt < 8; nt++) {
            int col = (int)colBase + wn*64 + nt*8 + c2;
            float b0 = bias[col], b1 = bias[col+1];
            float4 a = acc[mt][nt];
            float v0 = apply_epi(a.x + b0, EPI);
            float v1 = apply_epi(a.y + b1, EPI);
            float v2 = apply_epi(a.z + b0, EPI);
            float v3 = apply_epi(a.w + b1, EPI);
            *reinterpret_cast<float2*>(C + r0 * N + col) = make_float2(v0, v1);
            *reinterpret_cast<float2*>(C + r1 * N + col) = make_float2(v2, v3);
        }
    }
}

// ---------------- local windowed attention: one warp per (token, head) -----
__global__ __launch_bounds__(256) void local_attn_kernel(const int* __restrict__ pad)
{
    int gwarp = (blockIdx.x * blockDim.x + threadIdx.x) >> 5;
    int lane  = threadIdx.x & 31;
    if (gwarp >= Nt * Hc) return;
    int h = gwarp % Hc;
    int n = gwarp / Hc;      // b*S + q
    int b = n / Sc, q = n % Sc;

    const float* base = g_qkv + (long)n * (3*Ec);
    float2 qv = *reinterpret_cast<const float2*>(base + h*HDc + lane*2);

    float sc[4]; bool val[4];
#pragma unroll
    for (int w = 0; w < 4; w++) {
        int kpos = q - 3 + w;
        bool v = (kpos >= 0) && (pad[b*Sc + kpos] == 0);
        float s = 0.f;
        if (v) {
            float2 kv = *reinterpret_cast<const float2*>(
                g_qkv + ((long)(b*Sc + kpos)) * (3*Ec) + Ec + h*HDc + lane*2);
            s = qv.x*kv.x + qv.y*kv.y;
        }
#pragma unroll
        for (int o = 16; o > 0; o >>= 1) s += __shfl_xor_sync(0xffffffffu, s, o);
        sc[w]  = s * 0.125f;   // / sqrt(64)
        val[w] = v;
    }
    float m = -INFINITY;
#pragma unroll
    for (int w = 0; w < 4; w++) if (val[w]) m = fmaxf(m, sc[w]);
    float e[4]; float den = 0.f;
#pragma unroll
    for (int w = 0; w < 4; w++) { e[w] = val[w] ? expf(sc[w] - m) : 0.f; den += e[w]; }

    float2 o = make_float2(0.f, 0.f);
    if (den > 0.f) {
        float inv = 1.f / den;
#pragma unroll
        for (int w = 0; w < 4; w++) {
            if (!val[w]) continue;
            int kpos = q - 3 + w;
            float a = e[w] * inv;
            float2 vv = *reinterpret_cast<const float2*>(
                g_qkv + ((long)(b*Sc + kpos)) * (3*Ec) + 2*Ec + h*HDc + lane*2);
            o.x += a * vv.x; o.y += a * vv.y;
        }
    }
    *reinterpret_cast<float2*>(g_lo + (long)n*Ec + h*HDc + lane*2) = o;
}

// ---------------- valid length per batch ------------------------------------
__global__ void valid_len_kernel(const int* __restrict__ pad)
{
    int b = blockIdx.x;
    __shared__ int cnt;
    if (threadIdx.x == 0) cnt = 0;
    __syncthreads();
    int c = 0;
    for (int s = threadIdx.x; s < Sc; s += blockDim.x) c += (pad[b*Sc + s] != 0);
    atomicAdd(&cnt, c);
    __syncthreads();
    if (threadIdx.x == 0) {
        int v = Sc - cnt;
        g_vl[b] = v < 1 ? 1 : v;
    }
}

// ---------------- sampled positions: 32 lanes per token ---------------------
__global__ void sample_kernel()
{
    int idx = blockIdx.x * blockDim.x + threadIdx.x;
    int n = idx >> 5, p = idx & 31;
    if (n >= Nt) return;
    int b = n / Sc, s = n % Sc;

    float off = 0.f;   // mean over H then *OFFS(=8) == plain sum over H (exact)
#pragma unroll
    for (int h = 0; h < Hc; h++) off += g_offraw[(long)n*(Hc*Pc) + h*Pc + p];

    float pos    = (float)s;
    // fp32 emulation of jnp.linspace(0.1, 0.9, 32), endpoint exact
    float delta  = (0.9f - 0.1f) / 31.0f;
    float anchor = (p == 31) ? 0.9f : fmaf((float)p, delta, 0.1f);
    float samp   = anchor * pos + off;
    float lob    = fmaxf(pos - 256.f, 0.f);
    samp = fminf(fmaxf(samp, lob), pos);
    samp = fminf(samp, (float)(g_vl[b] - 1));
    g_sp[(long)n*Pc + p] = (int)rintf(samp);   // round-half-to-even == jnp.round
}

// ---------------- long deformable attention: one block per token ------------
__global__ __launch_bounds__(256) void long_attn_kernel(const int* __restrict__ pad)
{
    int n = blockIdx.x;            // token index
    int b = n / Sc, q = n % Sc;
    int tid = threadIdx.x, lane = tid & 31, warp = tid >> 5;

    __shared__ float s_sc[Pc];
    __shared__ float s_a[Pc];
    __shared__ int   s_j[Pc];
    if (tid < Pc) s_j[tid] = g_sp[(long)n*Pc + tid];
    __syncthreads();

    const float* qrow = g_qd + (long)n*Ec;
#pragma unroll
    for (int i = 0; i < 4; i++) {
        int p = warp*4 + i;
        int j = s_j[p];
        const float* krow = g_kd + ((long)b*Sc + j)*Ec;
        float s = 0.f;
#pragma unroll
        for (int t = 0; t < 4; t++) {
            float4 a = *reinterpret_cast<const float4*>(qrow + t*128 + lane*4);
            float4 k = *reinterpret_cast<const float4*>(krow + t*128 + lane*4);
            s += a.x*k.x + a.y*k.y + a.z*k.z + a.w*k.w;
        }
#pragma unroll
        for (int o = 16; o > 0; o >>= 1) s += __shfl_xor_sync(0xffffffffu, s, o);
        if (lane == 0) s_sc[p] = s;
    }
    __syncthreads();

    if (tid < Pc) {
        int p = tid;
        int j = s_j[p];
        int rb = q - 3; if (rb < 0) rb = 0;
        bool inv = (pad[b*Sc + j] != 0) || (j > q) || (j >= rb);
        float sc = inv ? -INFINITY : (s_sc[p] / 22.627416997969520780827019587355f);
        float m = sc;
#pragma unroll
        for (int o = 16; o > 0; o >>= 1) m = fmaxf(m, __shfl_xor_sync(0xffffffffu, m, o));
        float e = inv ? 0.f : expf(sc - m);
        float den = e;
#pragma unroll
        for (int o = 16; o > 0; o >>= 1) den += __shfl_xor_sync(0xffffffffu, den, o);
        s_a[p] = (den > 0.f) ? (e / den) : 0.f;
    }
    __syncthreads();

    int d = tid * 2;
    float a0 = 0.f, a1 = 0.f;
    for (int p = 0; p < Pc; p++) {
        float a = s_a[p];
        if (a != 0.f) {
            const float* vrow = g_vd + ((long)b*Sc + s_j[p])*Ec;
            float2 vv = *reinterpret_cast<const float2*>(vrow + d);
            a0 += a * vv.x; a1 += a * vv.y;
        }
    }
    *reinterpret_cast<float2*>(g_lattn + (long)n*Ec + d) = make_float2(a0, a1);
}

// ---------------- concat [x | local | long] ---------------------------------
__global__ void concat_kernel(const float* __restrict__ x)
{
    long i = (long)blockIdx.x * blockDim.x + threadIdx.x;
    if (i >= (long)Nt * (3*Ec)) return;
    long n = i / (3*Ec);
    int  c = (int)(i % (3*Ec));
    float v;
    if (c < Ec)           v = x[n*Ec + c];
    else if (c < 2*Ec)    v = g_local[n*Ec + c - Ec];
    else                  v = g_long[n*Ec + c - 2*Ec];
    g_cat[i] = v;
}

// ---------------- block reduction helper -------------------------------------
__device__ __forceinline__ float block_sum_256(float v)
{
    __shared__ float sh[8];
    int lane = threadIdx.x & 31, w = threadIdx.x >> 5;
#pragma unroll
    for (int o = 16; o > 0; o >>= 1) v += __shfl_xor_sync(0xffffffffu, v, o);
    if (lane == 0) sh[w] = v;
    __syncthreads();
    float r = (lane < 8) ? sh[lane] : 0.f;
    if (w == 0) {
#pragma unroll
        for (int o = 4; o > 0; o >>= 1) r += __shfl_xor_sync(0xffffffffu, r, o);
        if (lane == 0) sh[0] = r;
    }
    __syncthreads();
    float out = sh[0];
    __syncthreads();
    return out;
}

// ---------------- gate fuse + residual + LN1 --------------------------------
__global__ __launch_bounds__(256) void fuse_ln1_kernel(
    const float* __restrict__ x, const float* __restrict__ gW, const float* __restrict__ bW)
{
    int n = blockIdx.x, tid = threadIdx.x;
    long base = (long)n*Ec + tid*2;
    float2 gg = *reinterpret_cast<const float2*>(g_gate + base);
    float2 lc = *reinterpret_cast<const float2*>(g_local + base);
    float2 lg = *reinterpret_cast<const float2*>(g_long + base);
    float2 xx = *reinterpret_cast<const float2*>(x + base);
    float v0 = xx.x + gg.x*lc.x + (1.f - gg.x)*lg.x;
    float v1 = xx.y + gg.y*lc.y + (1.f - gg.y)*lg.y;

    float mean = block_sum_256(v0 + v1) * (1.f/512.f);
    float d0 = v0 - mean, d1 = v1 - mean;
    float var = block_sum_256(d0*d0 + d1*d1) * (1.f/512.f);
    float inv = 1.f / sqrtf(var + 1e-5f);

    int c = tid*2;
    float2 go = *reinterpret_cast<const float2*>(gW + c);
    float2 bo = *reinterpret_cast<const float2*>(bW + c);
    *reinterpret_cast<float2*>(g_x1 + base) =
        make_float2(d0*inv*go.x + bo.x, d1*inv*go.y + bo.y);
}

// ---------------- residual + LN2 (final output) ------------------------------
__global__ __launch_bounds__(256) void ln2_kernel(
    const float* __restrict__ gW, const float* __restrict__ bW, float* __restrict__ out)
{
    int n = blockIdx.x, tid = threadIdx.x;
    long base = (long)n*Ec + tid*2;
    float2 xa = *reinterpret_cast<const float2*>(g_x1 + base);
    float2 fa = *reinterpret_cast<const float2*>(g_f + base);
    float v0 = xa.x + fa.x, v1 = xa.y + fa.y;

    float mean = block_sum_256(v0 + v1) * (1.f/512.f);
    float d0 = v0 - mean, d1 = v1 - mean;
    float var = block_sum_256(d0*d0 + d1*d1) * (1.f/512.f);
    float inv = 1.f / sqrtf(var + 1e-5f);

    int c = tid*2;
    float2 go = *reinterpret_cast<const float2*>(gW + c);
    float2 bo = *reinterpret_cast<const float2*>(bW + c);
    *reinterpret_cast<float2*>(out + base) =
        make_float2(d0*inv*go.x + bo.x, d1*inv*go.y + bo.y);
}

// ---------------- host launcher ----------------------------------------------
static float* sym(const void* s) { void* p = nullptr; cudaGetSymbolAddress(&p, s); return (float*)p; }

extern "C" void kernel_launch(void* const* d_in, const int* in_sizes, int n_in,
                              void* d_out, int out_size)
{
    const float* x    = (const float*)d_in[0];
    const int*   pad  = (const int*)d_in[1];          // bool mask delivered as int32
    const float* in_proj_w = (const float*)d_in[2];
    const float* in_proj_b = (const float*)d_in[3];
    const float* mha_out_w = (const float*)d_in[4];
    const float* mha_out_b = (const float*)d_in[5];
    const float* dq_w = (const float*)d_in[6];
    const float* dq_b = (const float*)d_in[7];
    const float* dk_w = (const float*)d_in[8];
    const float* dk_b = (const float*)d_in[9];
    const float* dv_w = (const float*)d_in[10];
    const float* dv_b = (const float*)d_in[11];
    const float* do_w = (const float*)d_in[12];
    const float* do_b = (const float*)d_in[13];
    const float* off1_w = (const float*)d_in[14];
    const float* off1_b = (const float*)d_in[15];
    const float* off2_w = (const float*)d_in[16];
    const float* off2_b = (const float*)d_in[17];
    const float* gate1_w = (const float*)d_in[18];
    const float* gate1_b = (const float*)d_in[19];
    const float* gate2_w = (const float*)d_in[20];
    const float* gate2_b = (const float*)d_in[21];
    const float* n1_g = (const float*)d_in[22];
    const float* n1_b = (const float*)d_in[23];
    const float* n2_g = (const float*)d_in[24];
    const float* n2_b = (const float*)d_in[25];
    const float* ffn1_w = (const float*)d_in[26];
    const float* ffn1_b = (const float*)d_in[27];
    const float* ffn2_w = (const float*)d_in[28];
    const float* ffn2_b = (const float*)d_in[29];

    float* p_qkv   = sym(g_qkv);
    float* p_lo    = sym(g_lo);
    float* p_local = sym(g_local);
    float* p_h1    = sym(g_h1);
    float* p_offr  = sym(g_offraw);
    float* p_qd    = sym(g_qd);
    float* p_kd    = sym(g_kd);
    float* p_vd    = sym(g_vd);
    float* p_latt  = sym(g_lattn);
    float* p_long  = sym(g_long);
    float* p_cat   = sym(g_cat);
    float* p_gh    = sym(g_gh);
    float* p_gate  = sym(g_gate);
    float* p_x1    = sym(g_x1);
    float* p_ffnh  = sym(g_ffnh);
    float* p_f     = sym(g_f);

    dim3 blk(256);

    // 1) qkv = x @ in_proj_w^T + b   [8192,1536]
    tgemm<0><<<dim3(1536/128, Nt/128), blk>>>(x, in_proj_w, in_proj_b, p_qkv, Nt, 1536, Ec);
    // 2) local windowed attention -> g_lo
    local_attn_kernel<<<(Nt*Hc)/8, blk>>>(pad);
    // 3) local_out = lo @ mha_out_w^T + b
    tgemm<0><<<dim3(Ec/128, Nt/128), blk>>>(p_lo, mha_out_w, mha_out_b, p_local, Nt, Ec, Ec);
    // 4) offset path
    tgemm<1><<<dim3(Ec/128, Nt/128), blk>>>(x, off1_w, off1_b, p_h1, Nt, Ec, Ec);
    tgemm<2><<<dim3(256/128, Nt/128), blk>>>(p_h1, off2_w, off2_b, p_offr, Nt, 256, Ec);
    valid_len_kernel<<<Bc, blk>>>(pad);
    sample_kernel<<<(Nt*Pc)/256, blk>>>();
    // 5) deformable q/k/v projections
    tgemm<0><<<dim3(Ec/128, Nt/128), blk>>>(x, dq_w, dq_b, p_qd, Nt, Ec, Ec);
    tgemm<0><<<dim3(Ec/128, Nt/128), blk>>>(x, dk_w, dk_b, p_kd, Nt, Ec, Ec);
    tgemm<0><<<dim3(Ec/128, Nt/128), blk>>>(x, dv_w, dv_b, p_vd, Nt, Ec, Ec);
    // 6) long attention -> g_lattn
    long_attn_kernel<<<Nt, blk>>>(pad);
    // 7) long_out = lattn @ do_w^T + b
    tgemm<0><<<dim3(Ec/128, Nt/128), blk>>>(p_latt, do_w, do_b, p_long, Nt, Ec, Ec);
    // 8) gate
    concat_kernel<<<(int)(((long)Nt*3*Ec + 255)/256), blk>>>(x);
    tgemm<1><<<dim3(Ec/128, Nt/128), blk>>>(p_cat, gate1_w, gate1_b, p_gh, Nt, Ec, 3*Ec);
    tgemm<3><<<dim3(Ec/128, Nt/128), blk>>>(p_gh, gate2_w, gate2_b, p_gate, Nt, Ec, Ec);
    // 9) fuse + residual + LN1 -> g_x1
    fuse_ln1_kernel<<<Nt, blk>>>(x, n1_g, n1_b);
    // 10) FFN
    tgemm<1><<<dim3(HIDc/128, Nt/128), blk>>>(p_x1, ffn1_w, ffn1_b, p_ffnh, Nt, HIDc, Ec);
    tgemm<0><<<dim3(Ec/128, Nt/128), blk>>>(p_ffnh, ffn2_w, ffn2_b, p_f, Nt, Ec, HIDc);
    // 11) residual + LN2 -> output
    ln2_kernel<<<Nt, blk>>>(n2_g, n2_b, (float*)d_out);
}